// round 14
// baseline (speedup 1.0000x reference)
#include <cuda_runtime.h>
#include <cuda_bf16.h>
#include <cstdint>

#define NN 50000
#define EE 800000
#define DD 64
#define ET 6250                 // EE / 128
#define NT 391                  // ceil(NN / 128)
#define KP 136                  // node-kernel padded K stride (bf16)

// ---------------- device-global scratch (no allocations allowed) ----------
__device__ float g_agg[NN * DD];
__device__ float g_agg2[NN * DD];
__device__ float g_inv[NN];
__device__ int   g_cnt[NN];
__device__ float g_Wc[128 * 128];
__device__ float g_Px[NN * 128];   // per-node x @ Wc[0:64] + be1
__device__ int   g_is64;

__device__ __forceinline__ int load_row(const void* eidx, int i) {
    if (g_is64) return (int)((const long long*)eidx)[i];
    return ((const int*)eidx)[i];
}

// Prologue: zero BOTH agg buffers + cnt, detect eidx dtype.
__global__ void prolog_k(const void* eidx, float* agg1, float* agg2, int* cnt) {
    int i = blockIdx.x * blockDim.x + threadIdx.x;
    if (i < NN * DD / 4) {
        ((float4*)agg1)[i] = make_float4(0.f, 0.f, 0.f, 0.f);
        ((float4*)agg2)[i] = make_float4(0.f, 0.f, 0.f, 0.f);
    }
    if (i < NN) cnt[i] = 0;
    if (i == 0) {
        const long long* p = (const long long*)eidx;
        int ok = 1;
        for (int j = 0; j < 64; j++) {
            long long v = p[j];
            if (v < 0 || v >= NN) { ok = 0; break; }
        }
        g_is64 = ok;
    }
}

// Combine We1 halves + per-node edge count (cnt zeroed by prolog).
__global__ void combine_count_k(const float* __restrict__ We1, float* __restrict__ Wc,
                                const void* __restrict__ eidx, int* cnt) {
    int i = blockIdx.x * blockDim.x + threadIdx.x;
    if (i < 128 * 128) {
        int k = i >> 7, n = i & 127;
        float v = We1[(k + 64) * 128 + n];
        if (k < 64) v += We1[k * 128 + n];
        Wc[i] = v;
    }
    if (i < EE) atomicAdd(&cnt[load_row(eidx, i)], 1);
}

__global__ void inv_k(const int* __restrict__ cnt, float* __restrict__ inv) {
    int i = blockIdx.x * blockDim.x + threadIdx.x;
    if (i < NN) inv[i] = 1.0f / fmaxf((float)cnt[i], 1.0f);
}

// ---------------- helpers ---------------------------------------------------
__device__ __forceinline__ void split_pair(float f0, float f1, uint32_t& hi, uint32_t& lo) {
    asm("cvt.rn.bf16x2.f32 %0, %1, %2;" : "=r"(hi) : "f"(f1), "f"(f0));
    float h0 = __uint_as_float(hi << 16);
    float h1 = __uint_as_float(hi & 0xFFFF0000u);
    float r0 = f0 - h0;
    float r1 = f1 - h1;
    asm("cvt.rn.bf16x2.f32 %0, %1, %2;" : "=r"(lo) : "f"(r1), "f"(r0));
}

__device__ __forceinline__ void mma_bf16(float* d, const uint32_t* a, const uint32_t* b) {
    asm volatile(
        "mma.sync.aligned.m16n8k16.row.col.f32.bf16.bf16.f32 "
        "{%0,%1,%2,%3}, {%4,%5,%6,%7}, {%8,%9}, {%0,%1,%2,%3};"
        : "+f"(d[0]), "+f"(d[1]), "+f"(d[2]), "+f"(d[3])
        : "r"(a[0]), "r"(a[1]), "r"(a[2]), "r"(a[3]), "r"(b[0]), "r"(b[1]));
}

// ================= EDGE KERNEL: 32-row warps, fused chunking ===============
// 128 threads/CTA, 4 warps x 32 rows (2 m-tiles each). GEMM1 n-chunk (16
// cols) = GEMM2 k-chunk: compute acc1 chunk, relu+pack, feed GEMM2, discard.
// Halves per-row B-fragment LDS traffic (each B frag now feeds 6 MMAs).
#define E_SA   0                  // 32KB: raw ea -> (later) D2 staging
#define E_SW1  32768              // W1: 4 planes x 128 rows x 64B
#define E_SW2  65536              // W2: 8 planes x 64 rows x 64B
#define E_B2   98304              // 64 f32
#define E_RW   98560              // 128 int rows
#define E_SMEM 99072

__global__ void __launch_bounds__(128, 2)
edge_mma(const float* __restrict__ ea, const void* __restrict__ eidx,
         const float* __restrict__ Px,
         const float* __restrict__ Wc, const float* __restrict__ W2,
         const float* __restrict__ b2,
         float* __restrict__ dst, float* __restrict__ agg, int ntiles)
{
    extern __shared__ char smc[];
    float* sb2  = (float*)(smc + E_B2);
    int*   sRows = (int*)(smc + E_RW);

    const int tid = threadIdx.x;
    const int lane = tid & 31, w = tid >> 5;     // w in 0..3
    const int g = lane >> 2, qt = lane & 3;
    const int mrow0 = 32 * w + g;                // rows mrow0+8j, j=0..3

    // ---- stage W1 = Wc rows 64:127 (K=64) into planes 0..3 ----
    {
        const int n = tid;
        #pragma unroll
        for (int h = 0; h < 2; h++) {
            uint32_t hi[16], lo[16];
            #pragma unroll
            for (int p = 0; p < 16; p++) {
                int k = 32 * h + 2 * p;
                split_pair(Wc[(64 + k) * 128 + n], Wc[(64 + k + 1) * 128 + n], hi[p], lo[p]);
            }
            #pragma unroll
            for (int ksl = 0; ksl < 2; ksl++)
                #pragma unroll
                for (int q = 0; q < 4; q++) {
                    uint4 blk = make_uint4(hi[8 * ksl + q], hi[8 * ksl + q + 4],
                                           lo[8 * ksl + q], lo[8 * ksl + q + 4]);
                    *(uint4*)(smc + E_SW1 + (2 * h + ksl) * 8192 + n * 64 + q * 16) = blk;
                }
        }
    }
    // ---- stage W2 (64n x K=128) into planes 0..7 ----
    {
        const int n = tid & 63;
        const int kq0 = (tid >> 6) * 2;
        #pragma unroll
        for (int kq = kq0; kq < kq0 + 2; kq++) {
            uint32_t hi[16], lo[16];
            #pragma unroll
            for (int p = 0; p < 16; p++) {
                int k = 32 * kq + 2 * p;
                split_pair(W2[k * 64 + n], W2[(k + 1) * 64 + n], hi[p], lo[p]);
            }
            #pragma unroll
            for (int ksl = 0; ksl < 2; ksl++)
                #pragma unroll
                for (int q = 0; q < 4; q++) {
                    uint4 blk = make_uint4(hi[8 * ksl + q], hi[8 * ksl + q + 4],
                                           lo[8 * ksl + q], lo[8 * ksl + q + 4]);
                    *(uint4*)(smc + E_SW2 + (2 * kq + ksl) * 4096 + n * 64 + q * 16) = blk;
                }
        }
    }
    if (tid < 64) sb2[tid] = b2[tid];
    __syncthreads();

    // kernel-constant bases: GEMM loads are [base + literal]
    const char* pB1 = smc + E_SW1 + g * 64 + qt * 16;
    const char* pB2 = smc + E_SW2 + g * 64 + qt * 16;
    const int coff = qt >> 1, soff = 8 * (qt & 1);

    for (int tile = blockIdx.x; tile < ntiles; tile += gridDim.x) {
        const int i0 = tile * 128;

        sRows[tid] = load_row(eidx, i0 + tid);
        int r[4];
        #pragma unroll
        for (int j = 0; j < 4; j++)
            r[j] = load_row(eidx, i0 + mrow0 + 8 * j);

        // ---- phase 1: coalesced raw copy of ea tile (XOR chunk layout) ----
        {
            const uint4* src = (const uint4*)(ea + (size_t)i0 * DD);
            #pragma unroll
            for (int p = 0; p < 16; p++) {
                int id = p * 128 + tid;
                int row = id >> 4, c = id & 15;
                *(uint4*)(smc + E_SA + (row << 8) + (((c ^ (row & 15)) & 15) << 4)) = src[id];
            }
        }

        // ---- Px prefetch for chunk 0 ----
        const float* pr[4];
        #pragma unroll
        for (int j = 0; j < 4; j++)
            pr[j] = Px + (size_t)r[j] * 128 + 2 * qt;
        float pxb[2][2][4];
        #pragma unroll
        for (int mt = 0; mt < 2; mt++)
            #pragma unroll
            for (int t = 0; t < 2; t++) {
                float2 v0 = *(const float2*)(pr[2 * mt]     + 8 * t);
                float2 v1 = *(const float2*)(pr[2 * mt + 1] + 8 * t);
                pxb[mt][t][0] = v0.x; pxb[mt][t][1] = v0.y;
                pxb[mt][t][2] = v1.x; pxb[mt][t][3] = v1.y;
            }
        __syncthreads();

        // ---- phase 2: fragment-direct A converts (raw -> regs), 2 m-tiles --
        uint32_t aH[2][4][4], aL[2][4][4];
        #pragma unroll
        for (int mt = 0; mt < 2; mt++) {
            int ra = mrow0 + 16 * mt, rb = ra + 8;
            const char* pa = smc + E_SA + ra * 256;
            const char* pb = smc + E_SA + rb * 256;
            int xa = ra & 15, xb = rb & 15;
            #pragma unroll
            for (int ks = 0; ks < 4; ks++) {
                int c = 4 * ks + coff;
                float2 f0 = *(const float2*)(pa + (((c       ^ xa) & 15) << 4) + soff);
                float2 f1 = *(const float2*)(pb + (((c       ^ xb) & 15) << 4) + soff);
                float2 f2 = *(const float2*)(pa + ((((c + 2) ^ xa) & 15) << 4) + soff);
                float2 f3 = *(const float2*)(pb + ((((c + 2) ^ xb) & 15) << 4) + soff);
                split_pair(f0.x, f0.y, aH[mt][ks][0], aL[mt][ks][0]);
                split_pair(f1.x, f1.y, aH[mt][ks][1], aL[mt][ks][1]);
                split_pair(f2.x, f2.y, aH[mt][ks][2], aL[mt][ks][2]);
                split_pair(f3.x, f3.y, aH[mt][ks][3], aL[mt][ks][3]);
            }
        }
        __syncthreads();   // raw reads done -> sA reusable for D2 staging

        // ---- fused chunk loop: GEMM1 chunk -> relu/pack -> GEMM2 accumulate
        float acc2[2][8][4];
        #pragma unroll
        for (int mt = 0; mt < 2; mt++)
            #pragma unroll
            for (int nt = 0; nt < 8; nt++)
                #pragma unroll
                for (int j = 0; j < 4; j++) acc2[mt][nt][j] = 0.f;

        #pragma unroll
        for (int c = 0; c < 8; c++) {
            // acc1 chunk from prefetched Px
            float a1[2][2][4];
            #pragma unroll
            for (int mt = 0; mt < 2; mt++)
                #pragma unroll
                for (int t = 0; t < 2; t++)
                    #pragma unroll
                    for (int j = 0; j < 4; j++) a1[mt][t][j] = pxb[mt][t][j];
            // prefetch next chunk's Px
            if (c < 7) {
                #pragma unroll
                for (int mt = 0; mt < 2; mt++)
                    #pragma unroll
                    for (int t = 0; t < 2; t++) {
                        float2 v0 = *(const float2*)(pr[2 * mt]     + 8 * (2 * (c + 1) + t));
                        float2 v1 = *(const float2*)(pr[2 * mt + 1] + 8 * (2 * (c + 1) + t));
                        pxb[mt][t][0] = v0.x; pxb[mt][t][1] = v0.y;
                        pxb[mt][t][2] = v1.x; pxb[mt][t][3] = v1.y;
                    }
            }
            // GEMM1 for nt = 2c, 2c+1 (full K=64)
            #pragma unroll
            for (int ks = 0; ks < 4; ks++) {
                #pragma unroll
                for (int t = 0; t < 2; t++) {
                    uint4 B = *(const uint4*)(pB1 + ks * 8192 + (2 * c + t) * 512);
                    uint32_t bh[2] = {B.x, B.y}, bl[2] = {B.z, B.w};
                    mma_bf16(a1[0][t], aH[0][ks], bh);
                    mma_bf16(a1[0][t], aH[0][ks], bl);
                    mma_bf16(a1[0][t], aL[0][ks], bh);
                    mma_bf16(a1[1][t], aH[1][ks], bh);
                    mma_bf16(a1[1][t], aH[1][ks], bl);
                    mma_bf16(a1[1][t], aL[1][ks], bh);
                }
            }
            // relu + pack H fragments for GEMM2 k-step c
            uint32_t hA[2][4], lA[2][4];
            #pragma unroll
            for (int mt = 0; mt < 2; mt++) {
                float v00 = fmaxf(a1[mt][0][0], 0.f);
                float v01 = fmaxf(a1[mt][0][1], 0.f);
                float v02 = fmaxf(a1[mt][0][2], 0.f);
                float v03 = fmaxf(a1[mt][0][3], 0.f);
                float v10 = fmaxf(a1[mt][1][0], 0.f);
                float v11 = fmaxf(a1[mt][1][1], 0.f);
                float v12 = fmaxf(a1[mt][1][2], 0.f);
                float v13 = fmaxf(a1[mt][1][3], 0.f);
                split_pair(v00, v01, hA[mt][0], lA[mt][0]);
                split_pair(v02, v03, hA[mt][1], lA[mt][1]);
                split_pair(v10, v11, hA[mt][2], lA[mt][2]);
                split_pair(v12, v13, hA[mt][3], lA[mt][3]);
            }
            // GEMM2 accumulate for k-step c
            #pragma unroll
            for (int nt = 0; nt < 8; nt++) {
                uint4 B = *(const uint4*)(pB2 + c * 4096 + nt * 512);
                uint32_t bh[2] = {B.x, B.y}, bl[2] = {B.z, B.w};
                mma_bf16(acc2[0][nt], hA[0], bh);
                mma_bf16(acc2[0][nt], hA[0], bl);
                mma_bf16(acc2[0][nt], lA[0], bh);
                mma_bf16(acc2[1][nt], hA[1], bh);
                mma_bf16(acc2[1][nt], hA[1], bl);
                mma_bf16(acc2[1][nt], lA[1], bh);
            }
        }

        // ---- stage D2 into sA (XOR chunk layout, natural slot order) ----
        #pragma unroll
        for (int mt = 0; mt < 2; mt++) {
            int ra = mrow0 + 16 * mt, rb = ra + 8;
            #pragma unroll
            for (int nt = 0; nt < 8; nt++) {
                int cc = 2 * nt + (qt >> 1), s = qt & 1;
                uint32_t a0 = (uint32_t)(ra << 8) + ((uint32_t)((cc ^ (ra & 15)) & 15) << 4)
                            + ((uint32_t)s << 3);
                uint32_t a1a = (uint32_t)(rb << 8) + ((uint32_t)((cc ^ (rb & 15)) & 15) << 4)
                            + ((uint32_t)s << 3);
                *(float2*)(smc + E_SA + a0)  = make_float2(acc2[mt][nt][0], acc2[mt][nt][1]);
                *(float2*)(smc + E_SA + a1a) = make_float2(acc2[mt][nt][2], acc2[mt][nt][3]);
            }
        }
        __syncthreads();

        // ---- coalesced epilogue: red.v4 agg; dst = ea + (D2 + b2) ----
        {
            const float4* easrc = (const float4*)(ea + (size_t)i0 * DD);
            float4* dstp = (float4*)(dst + (size_t)i0 * DD);
            #pragma unroll
            for (int p = 0; p < 16; p++) {
                int id = p * 128 + tid;
                int row = id >> 4, c = id & 15;
                uint4 d = *(const uint4*)(smc + E_SA + (row << 8)
                                          + (((c ^ (row & 15)) & 15) << 4));
                float4 v;
                v.x = __uint_as_float(d.x) + sb2[4 * c + 0];
                v.y = __uint_as_float(d.y) + sb2[4 * c + 1];
                v.z = __uint_as_float(d.z) + sb2[4 * c + 2];
                v.w = __uint_as_float(d.w) + sb2[4 * c + 3];
                float* ap = agg + (size_t)sRows[row] * DD + 4 * c;
                asm volatile("red.global.add.v4.f32 [%0], {%1, %2, %3, %4};"
                             :: "l"(ap), "f"(v.x), "f"(v.y), "f"(v.z), "f"(v.w)
                             : "memory");
                float4 e = easrc[id];
                float4 o = make_float4(e.x + v.x, e.y + v.y, e.z + v.z, e.w + v.w);
                dstp[id] = o;
            }
        }
        __syncthreads();   // D2 reads done before next tile's raw copy
    }
}

// ---------------- node / px kernels (round-13, known good) -----------------
#define OFF_AH   0
#define OFF_AL   34816
#define OFF_W1H  69632
#define OFF_W1L  104448
#define OFF_W2H  139264
#define OFF_W2L  156672
#define OFF_B1   174080
#define OFF_B2   174592
#define SMEMSZ   175360

__global__ void __launch_bounds__(256, 1)
px_k(const float* __restrict__ x, const float* __restrict__ Wc,
     const float* __restrict__ be1, float* __restrict__ Px)
{
    extern __shared__ char smc[];
    uint16_t* sAh = (uint16_t*)(smc + OFF_AH);
    uint16_t* sAl = (uint16_t*)(smc + OFF_AL);
    uint16_t* sWh = (uint16_t*)(smc + OFF_W1H);
    uint16_t* sWl = (uint16_t*)(smc + OFF_W1L);
    float*    sb1 = (float*)(smc + OFF_B1);

    const int tid = threadIdx.x;
    const int lane = tid & 31, w = tid >> 5;
    const int g = lane >> 2, qt = lane & 3;
    const int wm = w >> 1, wn = w & 1;

    {
        int n = tid & 127, k0 = (tid >> 7) * 32;
        for (int k = k0; k < k0 + 32; k += 2) {
            uint32_t hi, lo;
            split_pair(Wc[k * 128 + n], Wc[(k + 1) * 128 + n], hi, lo);
            *(uint32_t*)&sWh[n * KP + k] = hi;
            *(uint32_t*)&sWl[n * KP + k] = lo;
        }
    }
    if (tid < 128) sb1[tid] = be1[tid];
    __syncthreads();

    for (int tile = blockIdx.x; tile < NT; tile += gridDim.x) {
        const int i0 = tile * 128;
        {
            const int m = tid & 127, ch = (tid >> 7) * 32;
            const int gi = i0 + m;
            const bool valid = gi < NN;
            const float* src = x + (size_t)(valid ? gi : 0) * DD + ch;
            #pragma unroll
            for (int c = 0; c < 32; c += 8) {
                float4 f0, f1;
                if (valid) { f0 = *(const float4*)(src + c); f1 = *(const float4*)(src + c + 4); }
                else { f0 = make_float4(0,0,0,0); f1 = f0; }
                uint32_t hw[4], lw[4];
                split_pair(f0.x, f0.y, hw[0], lw[0]);
                split_pair(f0.z, f0.w, hw[1], lw[1]);
                split_pair(f1.x, f1.y, hw[2], lw[2]);
                split_pair(f1.z, f1.w, hw[3], lw[3]);
                int e = m * KP + ch + c;
                *(uint4*)&sAh[e] = *(uint4*)hw;
                *(uint4*)&sAl[e] = *(uint4*)lw;
            }
        }
        __syncthreads();

        float acc[2][8][4];
        #pragma unroll
        for (int mt = 0; mt < 2; mt++)
            #pragma unroll
            for (int nt = 0; nt < 8; nt++)
                #pragma unroll
                for (int j = 0; j < 4; j++) acc[mt][nt][j] = 0.f;

        #pragma unroll
        for (int ks = 0; ks < 4; ks++) {
            const int kb = ks * 16 + 2 * qt;
            uint32_t ah[2][4], al[2][4];
            #pragma unroll
            for (int mt = 0; mt < 2; mt++) {
                int e = (wm * 32 + mt * 16 + g) * KP + kb;
                ah[mt][0] = *(const uint32_t*)&sAh[e];
                ah[mt][1] = *(const uint32_t*)&sAh[e + 8 * KP];
                ah[mt][2] = *(const uint32_t*)&sAh[e + 8];
                ah[mt][3] = *(const uint32_t*)&sAh[e + 8 * KP + 8];
                al[mt][0] = *(const uint32_t*)&sAl[e];
                al[mt][1] = *(const uint32_t*)&sAl[e + 8 * KP];
                al[mt][2] = *(const uint32_t*)&sAl[e + 8];
                al[mt][3] = *(const uint32_t*)&sAl[e + 8 * KP + 8];
            }
            #pragma unroll
            for (int nt = 0; nt < 8; nt++) {
                int e = (wn * 64 + nt * 8 + g) * KP + kb;
                uint32_t bh[2], bl[2];
                bh[0] = *(const uint32_t*)&sWh[e];
                bh[1] = *(const uint32_t*)&sWh[e + 8];
                bl[0] = *(const uint32_t*)&sWl[e];
                bl[1] = *(const uint32_t*)&sWl[e + 8];
                mma_bf16(acc[0][nt], ah[0], bh);
                mma_bf16(acc[1][nt], ah[1], bh);
                mma_bf16(acc[0][nt], ah[0], bl);
                mma_bf16(acc[1][nt], ah[1], bl);
                mma_bf16(acc[0][nt], al[0], bh);
                mma_bf16(acc[1][nt], al[1], bh);
            }
        }

        #pragma unroll
        for (int mt = 0; mt < 2; mt++)
            #pragma unroll
            for (int nt = 0; nt < 8; nt++) {
                int rl = wm * 32 + mt * 16 + g;
                int col = wn * 64 + nt * 8 + 2 * qt;
                #pragma unroll
                for (int rh = 0; rh < 2; rh++) {
                    int gi = i0 + rl + rh * 8;
                    if (gi >= NN) continue;
                    float2 v = make_float2(acc[mt][nt][rh * 2] + sb1[col],
                                           acc[mt][nt][rh * 2 + 1] + sb1[col + 1]);
                    *(float2*)&Px[(size_t)gi * 128 + col] = v;
                }
            }
        __syncthreads();
    }
}

__global__ void __launch_bounds__(256, 1)
node_mma(const float* __restrict__ x_src, const float* __restrict__ a_src,
         const float* __restrict__ W1, const float* __restrict__ b1,
         const float* __restrict__ W2, const float* __restrict__ b2,
         float* __restrict__ dst, const float* __restrict__ inv, int count)
{
    extern __shared__ char smc[];
    uint16_t* sAh  = (uint16_t*)(smc + OFF_AH);
    uint16_t* sAl  = (uint16_t*)(smc + OFF_AL);
    uint16_t* sW1h = (uint16_t*)(smc + OFF_W1H);
    uint16_t* sW1l = (uint16_t*)(smc + OFF_W1L);
    uint16_t* sW2h = (uint16_t*)(smc + OFF_W2H);
    uint16_t* sW2l = (uint16_t*)(smc + OFF_W2L);
    float*    sb1  = (float*)(smc + OFF_B1);
    float*    sb2  = (float*)(smc + OFF_B2);

    const int tid = threadIdx.x;
    const int lane = tid & 31, w = tid >> 5;
    const int g = lane >> 2, qt = lane & 3;
    const int wm = w >> 1, wn = w & 1;

    {
        int n = tid & 127, k0 = (tid >> 7) * 64;
        for (int k = k0; k < k0 + 64; k += 2) {
            uint32_t hi, lo;
            split_pair(W1[k * 128 + n], W1[(k + 1) * 128 + n], hi, lo);
            *(uint32_t*)&sW1h[n * KP + k] = hi;
            *(uint32_t*)&sW1l[n * KP + k] = lo;
        }
    }
    {
        int n = tid & 63, k0 = (tid >> 6) * 32;
        for (int k = k0; k < k0 + 32; k += 2) {
            uint32_t hi, lo;
            split_pair(W2[k * 64 + n], W2[(k + 1) * 64 + n], hi, lo);
            *(uint32_t*)&sW2h[n * KP + k] = hi;
            *(uint32_t*)&sW2l[n * KP + k] = lo;
        }
    }
    if (tid < 128) sb1[tid] = b1[tid];
    if (tid < 64)  sb2[tid] = b2[tid];
    __syncthreads();

    for (int tile = blockIdx.x; tile < NT; tile += gridDim.x) {
        const int i0 = tile * 128;
        {
            const int m = tid & 127, half = tid >> 7;
            const int gi = i0 + m;
            const bool valid = gi < count;
            const float* src;
            float scale = 1.0f;
            bool doscale = false;
            if (half == 0) {
                src = x_src + (size_t)(valid ? gi : 0) * DD;
            } else {
                src = a_src + (size_t)(valid ? gi : 0) * DD;
                scale = valid ? inv[gi] : 0.0f;
                doscale = true;
            }
            #pragma unroll
            for (int c = 0; c < 64; c += 8) {
                float4 f0 = *(const float4*)(src + c);
                float4 f1 = *(const float4*)(src + c + 4);
                if (doscale) {
                    f0.x *= scale; f0.y *= scale; f0.z *= scale; f0.w *= scale;
                    f1.x *= scale; f1.y *= scale; f1.z *= scale; f1.w *= scale;
                }
                uint32_t hw[4], lw[4];
                split_pair(f0.x, f0.y, hw[0], lw[0]);
                split_pair(f0.z, f0.w, hw[1], lw[1]);
                split_pair(f1.x, f1.y, hw[2], lw[2]);
                split_pair(f1.z, f1.w, hw[3], lw[3]);
                int e = m * KP + half * 64 + c;
                *(uint4*)&sAh[e] = *(uint4*)hw;
                *(uint4*)&sAl[e] = *(uint4*)lw;
            }
        }
        __syncthreads();

        float acc[2][8][4];
        #pragma unroll
        for (int mt = 0; mt < 2; mt++)
            #pragma unroll
            for (int nt = 0; nt < 8; nt++)
                #pragma unroll
                for (int j = 0; j < 4; j++) acc[mt][nt][j] = 0.f;

        #pragma unroll
        for (int ks = 0; ks < 8; ks++) {
            const int kb = ks * 16 + 2 * qt;
            uint32_t ah[2][4], al[2][4];
            #pragma unroll
            for (int mt = 0; mt < 2; mt++) {
                int e = (wm * 32 + mt * 16 + g) * KP + kb;
                ah[mt][0] = *(const uint32_t*)&sAh[e];
                ah[mt][1] = *(const uint32_t*)&sAh[e + 8 * KP];
                ah[mt][2] = *(const uint32_t*)&sAh[e + 8];
                ah[mt][3] = *(const uint32_t*)&sAh[e + 8 * KP + 8];
                al[mt][0] = *(const uint32_t*)&sAl[e];
                al[mt][1] = *(const uint32_t*)&sAl[e + 8 * KP];
                al[mt][2] = *(const uint32_t*)&sAl[e + 8];
                al[mt][3] = *(const uint32_t*)&sAl[e + 8 * KP + 8];
            }
            #pragma unroll
            for (int nt = 0; nt < 8; nt++) {
                int e = (wn * 64 + nt * 8 + g) * KP + kb;
                uint32_t bh[2], bl[2];
                bh[0] = *(const uint32_t*)&sW1h[e];
                bh[1] = *(const uint32_t*)&sW1h[e + 8];
                bl[0] = *(const uint32_t*)&sW1l[e];
                bl[1] = *(const uint32_t*)&sW1l[e + 8];
                mma_bf16(acc[0][nt], ah[0], bh);
                mma_bf16(acc[1][nt], ah[1], bh);
                mma_bf16(acc[0][nt], ah[0], bl);
                mma_bf16(acc[1][nt], ah[1], bl);
                mma_bf16(acc[0][nt], al[0], bh);
                mma_bf16(acc[1][nt], al[1], bh);
            }
        }
        __syncthreads();

        #pragma unroll
        for (int mt = 0; mt < 2; mt++)
            #pragma unroll
            for (int nt = 0; nt < 8; nt++) {
                int row = wm * 32 + mt * 16 + g;
                int col = wn * 64 + nt * 8 + 2 * qt;
                float v0 = fmaxf(acc[mt][nt][0] + sb1[col], 0.f);
                float v1 = fmaxf(acc[mt][nt][1] + sb1[col + 1], 0.f);
                float v2 = fmaxf(acc[mt][nt][2] + sb1[col], 0.f);
                float v3 = fmaxf(acc[mt][nt][3] + sb1[col + 1], 0.f);
                uint32_t hi, lo;
                split_pair(v0, v1, hi, lo);
                *(uint32_t*)&sAh[row * KP + col] = hi;
                *(uint32_t*)&sAl[row * KP + col] = lo;
                split_pair(v2, v3, hi, lo);
                *(uint32_t*)&sAh[(row + 8) * KP + col] = hi;
                *(uint32_t*)&sAl[(row + 8) * KP + col] = lo;
            }
        __syncthreads();

        float acc2[2][4][4];
        #pragma unroll
        for (int mt = 0; mt < 2; mt++)
            #pragma unroll
            for (int nt = 0; nt < 4; nt++)
                #pragma unroll
                for (int j = 0; j < 4; j++) acc2[mt][nt][j] = 0.f;

        #pragma unroll
        for (int ks = 0; ks < 8; ks++) {
            const int kb = ks * 16 + 2 * qt;
            uint32_t ah[2][4], al[2][4];
            #pragma unroll
            for (int mt = 0; mt < 2; mt++) {
                int e = (wm * 32 + mt * 16 + g) * KP + kb;
                ah[mt][0] = *(const uint32_t*)&sAh[e];
                ah[mt][1] = *(const uint32_t*)&sAh[e + 8 * KP];
                ah[mt][2] = *(const uint32_t*)&sAh[e + 8];
                ah[mt][3] = *(const uint32_t*)&sAh[e + 8 * KP + 8];
                al[mt][0] = *(const uint32_t*)&sAl[e];
                al[mt][1] = *(const uint32_t*)&sAl[e + 8 * KP];
                al[mt][2] = *(const uint32_t*)&sAl[e + 8];
                al[mt][3] = *(const uint32_t*)&sAl[e + 8 * KP + 8];
            }
            #pragma unroll
            for (int nt = 0; nt < 4; nt++) {
                int e = (wn * 32 + nt * 8 + g) * KP + kb;
                uint32_t bh[2], bl[2];
                bh[0] = *(const uint32_t*)&sW2h[e];
                bh[1] = *(const uint32_t*)&sW2h[e + 8];
                bl[0] = *(const uint32_t*)&sW2l[e];
                bl[1] = *(const uint32_t*)&sW2l[e + 8];
                mma_bf16(acc2[0][nt], ah[0], bh);
                mma_bf16(acc2[1][nt], ah[1], bh);
                mma_bf16(acc2[0][nt], ah[0], bl);
                mma_bf16(acc2[1][nt], ah[1], bl);
                mma_bf16(acc2[0][nt], al[0], bh);
                mma_bf16(acc2[1][nt], al[1], bh);
            }
        }

        #pragma unroll
        for (int mt = 0; mt < 2; mt++)
            #pragma unroll
            for (int nt = 0; nt < 4; nt++) {
                int rl = wm * 32 + mt * 16 + g;
                int col = wn * 32 + nt * 8 + 2 * qt;
                #pragma unroll
                for (int rh = 0; rh < 2; rh++) {
                    int row = rl + rh * 8;
                    int gi = i0 + row;
                    if (gi >= count) continue;
                    float vx = acc2[mt][nt][rh * 2 + 0] + sb2[col];
                    float vy = acc2[mt][nt][rh * 2 + 1] + sb2[col + 1];
                    float2 rv = *(const float2*)(x_src + (size_t)gi * DD + col);
                    *(float2*)(dst + (size_t)gi * DD + col) =
                        make_float2(rv.x + vx, rv.y + vy);
                }
            }
        __syncthreads();
    }
}

extern "C" void kernel_launch(void* const* d_in, const int* in_sizes, int n_in,
                              void* d_out, int out_size)
{
    const float* x   = (const float*)d_in[0];
    const float* ea  = (const float*)d_in[1];
    const float* We1 = (const float*)d_in[2];
    const float* be1 = (const float*)d_in[3];
    const float* We2 = (const float*)d_in[4];
    const float* be2 = (const float*)d_in[5];
    const float* Wn1 = (const float*)d_in[6];
    const float* bn1 = (const float*)d_in[7];
    const float* Wn2 = (const float*)d_in[8];
    const float* bn2 = (const float*)d_in[9];
    const void*  eidx = d_in[10];

    float* out_x  = (float*)d_out;
    float* out_ea = (float*)d_out + (size_t)NN * DD;

    float *agg, *agg2, *inv, *Wc, *Px;
    int* cnt;
    cudaGetSymbolAddress((void**)&agg,  g_agg);
    cudaGetSymbolAddress((void**)&agg2, g_agg2);
    cudaGetSymbolAddress((void**)&inv,  g_inv);
    cudaGetSymbolAddress((void**)&cnt,  g_cnt);
    cudaGetSymbolAddress((void**)&Wc,   g_Wc);
    cudaGetSymbolAddress((void**)&Px,   g_Px);

    cudaFuncSetAttribute(edge_mma, cudaFuncAttributeMaxDynamicSharedMemorySize, E_SMEM);
    cudaFuncSetAttribute(node_mma, cudaFuncAttributeMaxDynamicSharedMemorySize, SMEMSZ);
    cudaFuncSetAttribute(px_k,     cudaFuncAttributeMaxDynamicSharedMemorySize, SMEMSZ);

    int smcount = 148;
    cudaDeviceGetAttribute(&smcount, cudaDevAttrMultiProcessorCount, 0);
    int ge = 2 * smcount < ET ? 2 * smcount : ET;
    int gn = smcount < NT ? smcount : NT;

    // Edge kernel stays at my launch index 3 (profiled by ncu -s 5 -c 1).
    prolog_k<<<(NN * DD / 4 + 255) / 256, 256>>>(eidx, agg, agg2, cnt);      // 0
    combine_count_k<<<(EE + 255) / 256, 256>>>(We1, Wc, eidx, cnt);          // 1
    px_k<<<gn, 256, SMEMSZ>>>(x, Wc, be1, Px);                               // 2
    edge_mma<<<ge, 128, E_SMEM>>>(ea, eidx, Px, Wc, We2, be2,                // 3 <- profiled
                                  out_ea, agg, ET);
    inv_k<<<(NN + 255) / 256, 256>>>(cnt, inv);                              // 4
    node_mma<<<gn, 256, SMEMSZ>>>(x, agg, Wn1, bn1, Wn2, bn2,                // 5
                                  out_x, inv, NN);

    // iteration 2 (agg2 pre-zeroed in prolog -> no mid-stream zero pass)
    px_k<<<gn, 256, SMEMSZ>>>(out_x, Wc, be1, Px);                           // 6
    edge_mma<<<ge, 128, E_SMEM>>>(out_ea, eidx, Px, Wc, We2, be2,            // 7
                                  out_ea, agg2, ET);
    node_mma<<<gn, 256, SMEMSZ>>>(out_x, agg2, Wn1, bn1, Wn2, bn2,           // 8
                                  out_x, inv, NN);
}